// round 1
// baseline (speedup 1.0000x reference)
#include <cuda_runtime.h>
#include <cstdint>
#include <math.h>

// Problem dims
#define T_STEPS 512
#define B_SZ    64
#define H_SZ    512
#define D_SZ    32
#define NCOL    (7*H_SZ)      // 3584 gate columns
#define NTYPE   (D_SZ+1)      // 33 event types (incl. padding row)
#define PLANE   (T_STEPS*B_SZ*H_SZ)   // 16,777,216 elems per output array

// Persistent-kernel layout
#define NBLK    128
#define NTHR    256
#define KSPLIT  4
#define KSL     (H_SZ/KSPLIT) // 128 (K-slice per block)
#define CGROUPS 32
#define UPG     (H_SZ/CGROUPS) // 16 hidden units per column-group
#define WPAD    132            // padded k-stride for W in smem (bank-conflict-free)

#define SMEM_BYTES (116*1024)  // > 227KB/2 -> forces 1 block/SM (co-residency for grid barrier)

// -------- device globals (scratch; no allocation allowed) --------
__device__ float    g_tg[NTYPE*NCOL];          // type_gates = embed @ W_x + b  (472 KB)
__device__ float    g_h[B_SZ*H_SZ];            // recurrent h state (128 KB)
__device__ float    g_part[KSPLIT][B_SZ*NCOL]; // K-split partial GEMM results (3.67 MB)
__device__ unsigned g_arrive;
__device__ unsigned g_gen;

// ---------------- init kernel ----------------
// Builds type_gates table, copies h0 into state, resets barrier counters.
__global__ void hawkes_init(const float* __restrict__ embed,
                            const float* __restrict__ W,
                            const float* __restrict__ bg,
                            const float* __restrict__ h0)
{
    int idx = blockIdx.x*blockDim.x + threadIdx.x;
    if (idx == 0) { g_arrive = 0u; g_gen = 0u; }
    if (idx < B_SZ*H_SZ) g_h[idx] = h0[idx];
    if (idx < NTYPE*NCOL) {
        int ty  = idx / NCOL;
        int col = idx - ty*NCOL;
        float s = bg[col];
        #pragma unroll
        for (int d = 0; d < D_SZ; d++)
            s = fmaf(embed[ty*D_SZ + d], W[d*NCOL + col], s);
        g_tg[idx] = s;
    }
}

// ---------------- grid barrier ----------------
// Monotonic-generation barrier; no counter reset races. All 128 blocks are
// guaranteed co-resident (1 block/SM via smem footprint, 128 <= 148 SMs).
__device__ __forceinline__ void grid_bar(unsigned target)
{
    __syncthreads();
    if (threadIdx.x == 0) {
        __threadfence();
        unsigned old = atomicAdd(&g_arrive, 1u);
        if (old == (unsigned)NBLK*target - 1u) {
            atomicExch(&g_gen, target);          // release
        } else {
            while (*(volatile unsigned*)&g_gen < target) { __nanosleep(32); }
        }
        __threadfence();
    }
    __syncthreads();
}

__device__ __forceinline__ float sigmoidf_(float x) {
    return 1.0f / (1.0f + __expf(-x));
}

// ---------------- main persistent kernel ----------------
__global__ void __launch_bounds__(NTHR, 1)
hawkes_main(const float* __restrict__ seq_dt,
            const int*   __restrict__ seq_types,
            const float* __restrict__ W,
            const float* __restrict__ c0,
            const float* __restrict__ ct0,
            float* __restrict__ out)
{
    extern __shared__ float smem[];
    float* W_s = smem;                       // [7][UPG][WPAD]  = 59.1 KB
    float* h_s = smem + 7*UPG*WPAD;          // [B_SZ][KSL]     = 32 KB

    const int tid = threadIdx.x;
    const int bid = blockIdx.x;
    const int cg  = bid & (CGROUPS-1);       // column group 0..31
    const int ks  = bid >> 5;                // K-split 0..3
    const int u   = tid & 15;                // unit within group
    const int bq  = tid >> 4;                // batch quad 0..15

    // --- one-time: load loop-invariant W slice into smem ---
    // W_s[q][uu][k] = W_gates[D + ks*KSL + k][q*H + cg*UPG + uu]
    for (int i = tid; i < 7*UPG*KSL; i += NTHR) {
        int q  = i / (UPG*KSL);
        int r  = i - q*(UPG*KSL);
        int uu = r >> 7;             // / KSL
        int k  = r & (KSL-1);
        W_s[(q*UPG + uu)*WPAD + k] =
            W[(size_t)(D_SZ + ks*KSL + k)*NCOL + q*H_SZ + cg*UPG + uu];
    }

    // --- phase-B identity: this thread owns element (b_el, j_el) forever ---
    const int e    = bid*NTHR + tid;         // 0..32767 == b*H + j
    const int b_el = e >> 9;
    const int j_el = e & (H_SZ-1);
    float c    = c0[e];
    float ctar = ct0[e];

    const float4* g_h4 = (const float4*)g_h;
    float4*       h_s4 = (float4*)h_s;

    for (int t = 0; t < T_STEPS; t++) {
        // ---- stage h slice [B_SZ][KSL] from global (L2-coherent) ----
        for (int i = tid; i < B_SZ*(KSL/4); i += NTHR) {   // 2048 float4
            int b  = i >> 5;
            int kv = i & 31;
            h_s4[b*(KSL/4) + kv] = __ldcg(&g_h4[b*(H_SZ/4) + ks*(KSL/4) + kv]);
        }
        __syncthreads();

        // ---- phase A: partial GEMM  acc[b 4][gate 7] over this K slice ----
        float acc[4][7];
        #pragma unroll
        for (int i = 0; i < 4; i++)
            #pragma unroll
            for (int q = 0; q < 7; q++) acc[i][q] = 0.0f;

        #pragma unroll 2
        for (int k = 0; k < KSL; k += 4) {
            float4 hv[4];
            #pragma unroll
            for (int i = 0; i < 4; i++)
                hv[i] = *(const float4*)&h_s[(bq*4 + i)*KSL + k];
            float4 wv[7];
            #pragma unroll
            for (int q = 0; q < 7; q++)
                wv[q] = *(const float4*)&W_s[(q*UPG + u)*WPAD + k];
            #pragma unroll
            for (int i = 0; i < 4; i++)
                #pragma unroll
                for (int q = 0; q < 7; q++) {
                    acc[i][q] = fmaf(hv[i].x, wv[q].x, acc[i][q]);
                    acc[i][q] = fmaf(hv[i].y, wv[q].y, acc[i][q]);
                    acc[i][q] = fmaf(hv[i].z, wv[q].z, acc[i][q]);
                    acc[i][q] = fmaf(hv[i].w, wv[q].w, acc[i][q]);
                }
        }

        // store partials (coalesced over u within half-warp)
        #pragma unroll
        for (int i = 0; i < 4; i++) {
            int b = bq*4 + i;
            #pragma unroll
            for (int q = 0; q < 7; q++)
                g_part[ks][b*NCOL + q*H_SZ + cg*UPG + u] = acc[i][q];
        }

        grid_bar(2u*t + 1u);

        // ---- phase B: reduce K-splits, gates, state update, outputs ----
        {
            int   ty  = seq_types[t*B_SZ + b_el];
            float dtv = seq_dt  [t*B_SZ + b_el];

            float g[7];
            #pragma unroll
            for (int q = 0; q < 7; q++) {
                int col = q*H_SZ + j_el;
                float s = g_tg[ty*NCOL + col];
                #pragma unroll
                for (int k2 = 0; k2 < KSPLIT; k2++)
                    s += __ldcg(&g_part[k2][b_el*NCOL + col]);
                g[q] = s;
            }

            float inpt   = sigmoidf_(g[0]);
            float forget = sigmoidf_(g[1]);
            float outp   = sigmoidf_(g[2]);
            float in_tar = sigmoidf_(g[3]);
            float fg_tar = sigmoidf_(g[4]);
            float z      = tanhf(g[5]);
            // softplus(10*x)/10, numerically stable
            float y      = 10.0f * g[6];
            float decay  = 0.1f * (fmaxf(y, 0.0f) + log1pf(__expf(-fabsf(y))));

            float c_i      = forget*c + inpt*z;
            float ctar_new = fg_tar*ctar + in_tar*z;
            float edt      = __expf(-decay*dtv);
            float c_t      = ctar_new + (c_i - ctar_new)*edt;
            float h_t      = outp * tanhf(c_t);

            c    = c_t;
            ctar = ctar_new;

            g_h[e] = h_t;

            size_t base = (size_t)t*(B_SZ*H_SZ) + e;
            out[base + 0*(size_t)PLANE] = h_t;
            out[base + 1*(size_t)PLANE] = outp;
            out[base + 2*(size_t)PLANE] = c_i;
            out[base + 3*(size_t)PLANE] = ctar_new;
            out[base + 4*(size_t)PLANE] = decay;
        }

        grid_bar(2u*t + 2u);
    }
}

// ---------------- launch ----------------
extern "C" void kernel_launch(void* const* d_in, const int* in_sizes, int n_in,
                              void* d_out, int out_size)
{
    const float* seq_dt    = (const float*)d_in[0];
    const int*   seq_types = (const int*)  d_in[1];
    const float* embed     = (const float*)d_in[2];
    const float* W         = (const float*)d_in[3];
    const float* bg        = (const float*)d_in[4];
    const float* h0        = (const float*)d_in[5];
    const float* c0        = (const float*)d_in[6];
    const float* ct0       = (const float*)d_in[7];
    float* out = (float*)d_out;

    cudaFuncSetAttribute(hawkes_main,
                         cudaFuncAttributeMaxDynamicSharedMemorySize, SMEM_BYTES);

    // init: covers NTYPE*NCOL = 118272 work items exactly
    hawkes_init<<<(NTYPE*NCOL + 255)/256, 256>>>(embed, W, bg, h0);
    hawkes_main<<<NBLK, NTHR, SMEM_BYTES>>>(seq_dt, seq_types, W, c0, ct0, out);
}